// round 8
// baseline (speedup 1.0000x reference)
#include <cuda_runtime.h>

// UnfoldMatmulFold, fused gather. 4x4-px tile, CV=2, TPB=384 (warp==head),
// explicit row double-buffered vv pipeline, row-0 prefetch over staging sync.
//
// out[b,y,x,c] = sum over (h,kh),(w,kw) with 2h+kh=y+1, 2w+kw=x+1 of
//   sum_q attn[b,h,w,n,p=(kh,kw),q=(qh,qw)] * vv[b,2h+qh-1,2w+qw-1,c]
//
// attn staged to smem [patch][n][p][qh][4]: a qw-triple is one LDS.128.

namespace {

constexpr int Hc  = 28;
constexpr int Wc  = 28;
constexpr int Cch = 768;
constexpr int NH  = 12;
constexpr int GH  = 14;
constexpr int TPB = 384;                // 12 warps = 12 heads
constexpr int SEG = NH * 81;            // 972 floats per (b,h,w)
constexpr int SEG4 = SEG / 4;           // 243 float4s
constexpr int PATCH_W  = 9 * 3 * 4;     // 108 padded weights per head
constexpr int PATCH_SZ = NH * PATCH_W;  // 1296

// Row tables (R=4): per vv row r (0..6), entries (ph, qh, kh, oy), 2*ph+qh=r.
__device__ constexpr int RN [7]    = {2,2,5,3,4,1,1};
__device__ constexpr int RPH[7][5] = {{0,0,0,0,0},{0,0,0,0,0},{0,0,1,1,1},
                                      {1,1,1,0,0},{1,1,1,2,0},{2,0,0,0,0},{2,0,0,0,0}};
__device__ constexpr int RQH[7][5] = {{0,0,0,0,0},{1,1,0,0,0},{2,2,0,0,0},
                                      {1,1,1,0,0},{2,2,2,0,0},{1,0,0,0,0},{2,0,0,0,0}};
__device__ constexpr int RKH[7][5] = {{1,2,0,0,0},{1,2,0,0,0},{1,2,0,1,2},
                                      {0,1,2,0,0},{0,1,2,0,0},{0,0,0,0,0},{0,0,0,0,0}};
__device__ constexpr int ROY[7][5] = {{0,1,0,0,0},{0,1,0,0,0},{0,1,1,2,3},
                                      {1,2,3,0,0},{1,2,3,3,0},{3,0,0,0,0},{3,0,0,0,0}};

// Col tables (C=4): per patch-col pw, entries (kw, ox)
__device__ constexpr int CN [3]    = {2,3,1};
__device__ constexpr int CKW[3][3] = {{1,2,0},{0,1,2},{0,0,0}};
__device__ constexpr int COX[3][3] = {{0,1,0},{1,2,3},{3,0,0}};

__global__ __launch_bounds__(TPB, 2)
void fused_ufmf_kernel(const float* __restrict__ vv,
                       const float* __restrict__ attn,
                       float* __restrict__ out)
{
    const int t    = threadIdx.x;           // 0..383
    const int ty   = blockIdx.x / 7;
    const int tx   = blockIdx.x % 7;
    const int b    = blockIdx.y;

    const int y0   = 4 * ty;
    const int x0   = 4 * tx;
    const int n    = t >> 5;                // head == warp id
    const int lane = t & 31;
    const int c0   = n * 64 + lane * 2;     // 2 channels per thread

    __shared__ __align__(16) float s_w[9 * PATCH_SZ];   // 46656 B

    const float* vbase = vv + (size_t)b * (Hc * Wc * Cch) + c0;

    // Row pipeline buffers (registers); OOB positions zero-filled.
    float2 vbuf[2][7];

#define LOADROW(P, R)                                                         \
    do {                                                                      \
        const int gy_ = y0 - 1 + (R);                                         \
        const bool rok_ = (unsigned)gy_ < (unsigned)Hc;                       \
        _Pragma("unroll")                                                     \
        for (int s_ = 0; s_ < 7; ++s_) {                                      \
            const int gx_ = x0 - 1 + s_;                                      \
            if (rok_ && ((unsigned)gx_ < (unsigned)Wc))                       \
                vbuf[P][s_] = *reinterpret_cast<const float2*>(               \
                    vbase + (unsigned)((gy_ * Wc + gx_) * Cch));              \
            else vbuf[P][s_] = make_float2(0.f, 0.f);                         \
        }                                                                     \
    } while (0)

    // Prefetch row 0 before the staging barrier: overlaps attn staging.
    LOADROW(0, 0);

    // ---- Stage attn for 9 patches (threads 0..242; indices hoisted) ----
    if (t < SEG4) {
        int dst[4];
#pragma unroll
        for (int j = 0; j < 4; ++j) {
            const int i   = 4 * t + j;
            const int nn  = i / 81;
            const int rem = i - nn * 81;
            const int p   = rem / 9;
            const int q   = rem - p * 9;
            dst[j] = nn * PATCH_W + p * 12 + q + q / 3;
        }
#pragma unroll
        for (int patch = 0; patch < 9; ++patch) {
            const int ph = patch / 3, pw = patch % 3;
            const int h = 2 * ty + ph, w = 2 * tx + pw;
            const bool val = (h < GH) && (w < GH);
            const int hs = val ? h : 0, ws = val ? w : 0;
            const float4* g4 = reinterpret_cast<const float4*>(
                attn + ((size_t)((b * GH + hs) * GH + ws)) * SEG);
            float4 x4 = make_float4(0.f, 0.f, 0.f, 0.f);
            if (val) x4 = __ldg(g4 + t);
            float* sp = s_w + patch * PATCH_SZ;
            sp[dst[0]] = x4.x; sp[dst[1]] = x4.y;
            sp[dst[2]] = x4.z; sp[dst[3]] = x4.w;
        }
    }
    __syncthreads();

    float2 acc[4][4];
#pragma unroll
    for (int i = 0; i < 4; ++i)
#pragma unroll
        for (int j = 0; j < 4; ++j) acc[i][j] = make_float2(0.f, 0.f);

    const float* swn = s_w + n * PATCH_W;

#define COMPROW(P, R)                                                         \
    do {                                                                      \
        _Pragma("unroll")                                                     \
        for (int e = 0; e < RN[R]; ++e) {                                     \
            const int ph = RPH[R][e], qh = RQH[R][e];                         \
            const int kh = RKH[R][e], oy = ROY[R][e];                         \
            _Pragma("unroll")                                                 \
            for (int pw = 0; pw < 3; ++pw) {                                  \
                _Pragma("unroll")                                             \
                for (int f = 0; f < CN[pw]; ++f) {                            \
                    const int kw = CKW[pw][f], ox = COX[pw][f];               \
                    const float4 w4 = *reinterpret_cast<const float4*>(       \
                        swn + (ph * 3 + pw) * PATCH_SZ                        \
                            + (kh * 3 + kw) * 12 + qh * 4);                   \
                    float2& a = acc[oy][ox];                                  \
                    a.x += w4.x * vbuf[P][2*pw  ].x;                          \
                    a.y += w4.x * vbuf[P][2*pw  ].y;                          \
                    a.x += w4.y * vbuf[P][2*pw+1].x;                          \
                    a.y += w4.y * vbuf[P][2*pw+1].y;                          \
                    a.x += w4.z * vbuf[P][2*pw+2].x;                          \
                    a.y += w4.z * vbuf[P][2*pw+2].y;                          \
                }                                                             \
            }                                                                 \
        }                                                                     \
    } while (0)

    LOADROW(1, 1); COMPROW(0, 0);
    LOADROW(0, 2); COMPROW(1, 1);
    LOADROW(1, 3); COMPROW(0, 2);
    LOADROW(0, 4); COMPROW(1, 3);
    LOADROW(1, 5); COMPROW(0, 4);
    LOADROW(0, 6); COMPROW(1, 5);
    COMPROW(0, 6);

#undef LOADROW
#undef COMPROW

    // ---- Stores: each output element produced exactly once ----
    float* obase = out + (size_t)b * (Hc * Wc * Cch) + c0;
#pragma unroll
    for (int oy = 0; oy < 4; ++oy)
#pragma unroll
        for (int ox = 0; ox < 4; ++ox)
            *reinterpret_cast<float2*>(
                obase + (unsigned)((((y0 + oy) * Wc) + (x0 + ox)) * Cch)) = acc[oy][ox];
}

} // namespace

extern "C" void kernel_launch(void* const* d_in, const int* in_sizes, int n_in,
                              void* d_out, int out_size)
{
    const float* vv   = (const float*)d_in[0];
    const float* attn = (const float*)d_in[1];
    float* out        = (float*)d_out;

    dim3 grid(7 * 7, 64);   // (ty,tx) 4x4 tiles x batch
    fused_ufmf_kernel<<<grid, TPB>>>(vv, attn, out);
}

// round 9
// speedup vs baseline: 1.0142x; 1.0142x over previous
#include <cuda_runtime.h>

// UnfoldMatmulFold, fused gather. 4x4-px tile, CV=2, TPB=384 (warp==head).
// Split into interior kernel (no bounds checks, 25/49 tiles) and edge kernel.
//
// out[b,y,x,c] = sum over (h,kh),(w,kw) with 2h+kh=y+1, 2w+kw=x+1 of
//   sum_q attn[b,h,w,n,p=(kh,kw),q=(qh,qw)] * vv[b,2h+qh-1,2w+qw-1,c]
//
// attn staged to smem [patch][n][p][qh][4]: a qw-triple is one LDS.128.

namespace {

constexpr int Hc  = 28;
constexpr int Wc  = 28;
constexpr int Cch = 768;
constexpr int NH  = 12;
constexpr int GH  = 14;
constexpr int TPB = 384;                // 12 warps = 12 heads
constexpr int SEG = NH * 81;            // 972 floats per (b,h,w)
constexpr int SEG4 = SEG / 4;           // 243 float4s
constexpr int PATCH_W  = 9 * 3 * 4;     // 108 padded weights per head
constexpr int PATCH_SZ = NH * PATCH_W;  // 1296

// Row tables (R=4): per vv row r (0..6), entries (ph, qh, kh, oy), 2*ph+qh=r.
__device__ constexpr int RN [7]    = {2,2,5,3,4,1,1};
__device__ constexpr int RPH[7][5] = {{0,0,0,0,0},{0,0,0,0,0},{0,0,1,1,1},
                                      {1,1,1,0,0},{1,1,1,2,0},{2,0,0,0,0},{2,0,0,0,0}};
__device__ constexpr int RQH[7][5] = {{0,0,0,0,0},{1,1,0,0,0},{2,2,0,0,0},
                                      {1,1,1,0,0},{2,2,2,0,0},{1,0,0,0,0},{2,0,0,0,0}};
__device__ constexpr int RKH[7][5] = {{1,2,0,0,0},{1,2,0,0,0},{1,2,0,1,2},
                                      {0,1,2,0,0},{0,1,2,0,0},{0,0,0,0,0},{0,0,0,0,0}};
__device__ constexpr int ROY[7][5] = {{0,1,0,0,0},{0,1,0,0,0},{0,1,1,2,3},
                                      {1,2,3,0,0},{1,2,3,3,0},{3,0,0,0,0},{3,0,0,0,0}};

// Col tables (C=4): per patch-col pw, entries (kw, ox)
__device__ constexpr int CN [3]    = {2,3,1};
__device__ constexpr int CKW[3][3] = {{1,2,0},{0,1,2},{0,0,0}};
__device__ constexpr int COX[3][3] = {{0,1,0},{1,2,3},{3,0,0}};

// Shared compute body: stages attn, runs the 7-row loop, stores the 4x4 tile.
// INTERIOR=true assumes all vv rows/cols and all 9 patches are in range.
template <bool INTERIOR>
__device__ __forceinline__ void tile_body(const float* __restrict__ vv,
                                          const float* __restrict__ attn,
                                          float* __restrict__ out,
                                          int b, int ty, int tx)
{
    const int t    = threadIdx.x;           // 0..383
    const int y0   = 4 * ty;
    const int x0   = 4 * tx;
    const int n    = t >> 5;                // head == warp id
    const int lane = t & 31;
    const int c0   = n * 64 + lane * 2;     // 2 channels per thread

    __shared__ __align__(16) float s_w[9 * PATCH_SZ];   // 46656 B

    // ---- Stage attn for 9 patches (threads 0..242; indices hoisted) ----
    if (t < SEG4) {
        int dst[4];
#pragma unroll
        for (int j = 0; j < 4; ++j) {
            const int i   = 4 * t + j;
            const int nn  = i / 81;
            const int rem = i - nn * 81;
            const int p   = rem / 9;
            const int q   = rem - p * 9;
            dst[j] = nn * PATCH_W + p * 12 + q + q / 3;
        }
#pragma unroll
        for (int patch = 0; patch < 9; ++patch) {
            const int ph = patch / 3, pw = patch % 3;
            const int h = 2 * ty + ph, w = 2 * tx + pw;
            float4 x4;
            if (INTERIOR) {
                x4 = __ldg(reinterpret_cast<const float4*>(
                        attn + ((size_t)((b * GH + h) * GH + w)) * SEG) + t);
            } else {
                const bool val = (h < GH) && (w < GH);
                const int hs = val ? h : 0, ws = val ? w : 0;
                x4 = make_float4(0.f, 0.f, 0.f, 0.f);
                if (val)
                    x4 = __ldg(reinterpret_cast<const float4*>(
                            attn + ((size_t)((b * GH + hs) * GH + ws)) * SEG) + t);
            }
            float* sp = s_w + patch * PATCH_SZ;
            sp[dst[0]] = x4.x; sp[dst[1]] = x4.y;
            sp[dst[2]] = x4.z; sp[dst[3]] = x4.w;
        }
    }
    __syncthreads();

    float2 acc[4][4];
#pragma unroll
    for (int i = 0; i < 4; ++i)
#pragma unroll
        for (int j = 0; j < 4; ++j) acc[i][j] = make_float2(0.f, 0.f);

    const float* vbase = vv + (size_t)b * (Hc * Wc * Cch) + c0;
    const float* swn   = s_w + n * PATCH_W;

#pragma unroll
    for (int r = 0; r < 7; ++r) {
        const int gy = y0 - 1 + r;

        float2 v[7];
        if (INTERIOR) {
            const float* rowp = vbase + (unsigned)(gy * (Wc * Cch)) + (unsigned)((x0 - 1) * Cch);
#pragma unroll
            for (int s = 0; s < 7; ++s)
                v[s] = *reinterpret_cast<const float2*>(rowp + s * Cch);
        } else {
            const bool rok = (unsigned)gy < (unsigned)Hc;
#pragma unroll
            for (int s = 0; s < 7; ++s) {
                const int gx = x0 - 1 + s;
                if (rok && ((unsigned)gx < (unsigned)Wc))
                    v[s] = *reinterpret_cast<const float2*>(
                        vbase + (unsigned)((gy * Wc + gx) * Cch));
                else
                    v[s] = make_float2(0.f, 0.f);
            }
        }

#pragma unroll
        for (int e = 0; e < RN[r]; ++e) {
            const int ph = RPH[r][e], qh = RQH[r][e];
            const int kh = RKH[r][e], oy = ROY[r][e];
#pragma unroll
            for (int pw = 0; pw < 3; ++pw) {
#pragma unroll
                for (int f = 0; f < CN[pw]; ++f) {
                    const int kw = CKW[pw][f], ox = COX[pw][f];
                    const float4 w4 = *reinterpret_cast<const float4*>(
                        swn + (ph * 3 + pw) * PATCH_SZ
                            + (kh * 3 + kw) * 12 + qh * 4);
                    float2& a = acc[oy][ox];
                    a.x += w4.x * v[2*pw  ].x;  a.y += w4.x * v[2*pw  ].y;
                    a.x += w4.y * v[2*pw+1].x;  a.y += w4.y * v[2*pw+1].y;
                    a.x += w4.z * v[2*pw+2].x;  a.y += w4.z * v[2*pw+2].y;
                }
            }
        }
    }

    // ---- Stores: each output element produced exactly once ----
    float* obase = out + (size_t)b * (Hc * Wc * Cch) + c0;
#pragma unroll
    for (int oy = 0; oy < 4; ++oy)
#pragma unroll
        for (int ox = 0; ox < 4; ++ox)
            *reinterpret_cast<float2*>(
                obase + (unsigned)((((y0 + oy) * Wc) + (x0 + ox)) * Cch)) = acc[oy][ox];
}

__global__ __launch_bounds__(TPB, 2)
void ufmf_interior_kernel(const float* __restrict__ vv,
                          const float* __restrict__ attn,
                          float* __restrict__ out)
{
    const int i  = blockIdx.x;          // 0..24
    const int ty = 1 + i / 5;           // 1..5
    const int tx = 1 + i % 5;           // 1..5
    tile_body<true>(vv, attn, out, blockIdx.y, ty, tx);
}

__global__ __launch_bounds__(TPB, 2)
void ufmf_edge_kernel(const float* __restrict__ vv,
                      const float* __restrict__ attn,
                      float* __restrict__ out)
{
    const int e = blockIdx.x;           // 0..23 perimeter cells of 7x7
    int ty, tx;
    if (e < 7)       { ty = 0;      tx = e;      }
    else if (e < 14) { ty = 6;      tx = e - 7;  }
    else if (e < 19) { ty = e - 13; tx = 0;      }   // 1..5
    else             { ty = e - 18; tx = 6;      }   // 1..5
    tile_body<false>(vv, attn, out, blockIdx.y, ty, tx);
}

} // namespace

extern "C" void kernel_launch(void* const* d_in, const int* in_sizes, int n_in,
                              void* d_out, int out_size)
{
    const float* vv   = (const float*)d_in[0];
    const float* attn = (const float*)d_in[1];
    float* out        = (float*)d_out;

    ufmf_interior_kernel<<<dim3(25, 64), TPB>>>(vv, attn, out);
    ufmf_edge_kernel<<<dim3(24, 64), TPB>>>(vv, attn, out);
}